// round 12
// baseline (speedup 1.0000x reference)
#include <cuda_runtime.h>
#include <cstdint>

#define BB 96
#define HH 100
#define NN 128
#define DD 768
#define AA 256
#define LDH (HH * DD)        // hist batch stride
#define PS  (BB * DD)        // 73728: partial slot stride for N=768
#define PSQ (BB * AA)        // 24576: partial slot stride for N=256

// ---------------- scratch ----------------
__device__ float g_neigh[BB * DD];
__device__ float g_hbar [BB * DD];
__device__ float g_part [72 * PS];       // slots: 0..23 bias, 24..47 u/out, 48..71 R
__device__ float g_partQ[24 * PSQ];
__device__ float g_partP[8 * PS];

// ---------------- f32x2 helpers ----------------
typedef unsigned long long ull;
__device__ __forceinline__ ull pk2(float x) {
    ull r; asm("mov.b64 %0, {%1, %1};" : "=l"(r) : "f"(x)); return r;
}
__device__ __forceinline__ void ffma2(ull& d, ull a, ull b) {
    asm("fma.rn.f32x2 %0, %1, %2, %0;" : "+l"(d) : "l"(a), "l"(b));
}
__device__ __forceinline__ float2 up2(ull v) {
    float2 r; asm("mov.b64 {%0, %1}, %2;" : "=f"(r.x), "=f"(r.y) : "l"(v)); return r;
}

// ---------------- neigh = mean_{h<96} hist[b,h,:] ----------------
__global__ void k_neigh(const float* __restrict__ hist) {
    int b = blockIdx.x, d = threadIdx.x;             // 768 threads
    const float* p = hist + (size_t)b * LDH + d;
    float s = 0.f;
#pragma unroll 8
    for (int h = 0; h < BB; ++h) s += p[h * DD];
    g_neigh[b * DD + d] = s * (1.0f / BB);
}

// ======== shared GEMM core: f32x2 compute from As/Bs + store =========
// thread tile 6m x 4n; 16 x 32 thread grid; writes partial tile to po.
#define GEMM_COMPUTE_STORE(po, NVAL)                                          \
    __syncthreads();                                                          \
    {                                                                         \
        const int mI = tid >> 5, nI = tid & 31;                               \
        ull acc[6][2];                                                        \
        _Pragma("unroll") for (int i = 0; i < 6; ++i)                         \
        { acc[i][0] = 0ULL; acc[i][1] = 0ULL; }                               \
        _Pragma("unroll") for (int k = 0; k < 32; ++k) {                      \
            float2 a01 = *(const float2*)&As[k][6 * mI];                      \
            float2 a23 = *(const float2*)&As[k][6 * mI + 2];                  \
            float2 a45 = *(const float2*)&As[k][6 * mI + 4];                  \
            ulonglong2 bb = *(const ulonglong2*)&Bs[k][4 * nI];               \
            ull ap0 = pk2(a01.x), ap1 = pk2(a01.y), ap2 = pk2(a23.x);         \
            ull ap3 = pk2(a23.y), ap4 = pk2(a45.x), ap5 = pk2(a45.y);         \
            ffma2(acc[0][0], ap0, bb.x); ffma2(acc[0][1], ap0, bb.y);         \
            ffma2(acc[1][0], ap1, bb.x); ffma2(acc[1][1], ap1, bb.y);         \
            ffma2(acc[2][0], ap2, bb.x); ffma2(acc[2][1], ap2, bb.y);         \
            ffma2(acc[3][0], ap3, bb.x); ffma2(acc[3][1], ap3, bb.y);         \
            ffma2(acc[4][0], ap4, bb.x); ffma2(acc[4][1], ap4, bb.y);         \
            ffma2(acc[5][0], ap5, bb.x); ffma2(acc[5][1], ap5, bb.y);         \
        }                                                                     \
        _Pragma("unroll") for (int i = 0; i < 6; ++i) {                       \
            int m = 6 * mI + i;                                               \
            float2 lo = up2(acc[i][0]), hi = up2(acc[i][1]);                  \
            float4 v = make_float4(lo.x, lo.y, hi.x, hi.y);                   \
            *(float4*)&(po)[(size_t)m * (NVAL) + 4 * nI] = v;                 \
        }                                                                     \
    }

// helper macros for the standard B loads
#define LOAD_B_T(Bp, Kv)                                                      \
    float2 vb[4];                                                             \
    _Pragma("unroll") for (int j = 0; j < 4; ++j) {                           \
        int idx = tid + 512 * j; int n = idx >> 4, c = idx & 15;              \
        vb[j] = *(const float2*)((Bp) + (size_t)(blockIdx.x * 128 + n) * (Kv) \
                                 + kb + 2 * c);                               \
    }                                                                         \
    _Pragma("unroll") for (int j = 0; j < 4; ++j) {                           \
        int idx = tid + 512 * j; int n = idx >> 4, c = idx & 15;              \
        Bs[2 * c][n] = vb[j].x; Bs[2 * c + 1][n] = vb[j].y;                   \
    }

#define LOAD_B_NT(Bp, ldbv)                                                   \
    float4 wb[2];                                                             \
    _Pragma("unroll") for (int j = 0; j < 2; ++j) {                           \
        int vidx = tid + 512 * j; int k = vidx >> 5, nv = vidx & 31;          \
        wb[j] = *(const float4*)((Bp) + (size_t)(kb + k) * (ldbv)             \
                                 + blockIdx.x * 128 + 4 * nv);                \
    }                                                                         \
    _Pragma("unroll") for (int j = 0; j < 2; ++j) {                           \
        int vidx = tid + 512 * j; int k = vidx >> 5, nv = vidx & 31;          \
        *(float4*)&Bs[k][4 * nv] = wb[j];                                     \
    }

#define STORE_A()                                                             \
    _Pragma("unroll") for (int j = 0; j < 3; ++j) {                           \
        int idx = tid + 512 * j; int m = idx >> 4, c = idx & 15;              \
        As[2 * c][m] = va[j].x; As[2 * c + 1][m] = va[j].y;                   \
    }

// ---- stage A (2 jobs, T): slots 0..23 = neigh@Wl^T; 24..47 = hist0@Wr^T
__global__ void __launch_bounds__(512, 1)
k_sgemmA(const float* __restrict__ neigh, const float* __restrict__ Wl,
         const float* __restrict__ hist, const float* __restrict__ Wr) {
    __shared__ float As[32][98];
    __shared__ float Bs[32][132];
    const int tid = threadIdx.x;
    const int kb = blockIdx.y * 32;
    const int z = blockIdx.z;
    const float* A = z ? hist : neigh;
    const float* B = z ? Wr : Wl;
    const int lda = z ? LDH : DD;

    float2 va[3];
#pragma unroll
    for (int j = 0; j < 3; ++j) {
        int idx = tid + 512 * j; int m = idx >> 4, c = idx & 15;
        va[j] = *(const float2*)(A + (size_t)m * lda + kb + 2 * c);
    }
    LOAD_B_T(B, DD)
    STORE_A()
    float* po = g_part + (size_t)(z * 24 + blockIdx.y) * PS + blockIdx.x * 128;
    GEMM_COMPUTE_STORE(po, DD)
}

// ---- stage Q (T): A = sum(48 slots) + bl[k]; B = WQ; out g_partQ ----
__global__ void __launch_bounds__(512, 1)
k_sgemmQf(const float* __restrict__ bl, const float* __restrict__ WQ) {
    __shared__ float As[32][98];
    __shared__ float Bs[32][132];
    const int tid = threadIdx.x;
    const int kb = blockIdx.y * 32;

    float2 va[3];
#pragma unroll
    for (int j = 0; j < 3; ++j) {
        int idx = tid + 512 * j; int m = idx >> 4, c = idx & 15;
        const float* base = g_part + (size_t)m * DD + kb + 2 * c;
        float2 s = *(const float2*)(bl + kb + 2 * c);
#pragma unroll 4
        for (int sl = 0; sl < 48; ++sl) {
            float2 v = *(const float2*)(base + (size_t)sl * PS);
            s.x += v.x; s.y += v.y;
        }
        va[j] = s;
    }
    LOAD_B_T(WQ, DD)
    STORE_A()
    float* po = g_partQ + (size_t)blockIdx.y * PSQ + blockIdx.x * 128;
    GEMM_COMPUTE_STORE(po, AA)
}

// ---- stage P (NT): A = sum(24 Q-slots) + bQ[k]; B = WK; out g_partP -
__global__ void __launch_bounds__(512, 1)
k_sgemmPf(const float* __restrict__ bQ, const float* __restrict__ WK) {
    __shared__ float As[32][98];
    __shared__ float Bs[32][132];
    const int tid = threadIdx.x;
    const int kb = blockIdx.y * 32;

    float2 va[3];
#pragma unroll
    for (int j = 0; j < 3; ++j) {
        int idx = tid + 512 * j; int m = idx >> 4, c = idx & 15;
        const float* base = g_partQ + (size_t)m * AA + kb + 2 * c;
        float2 s = *(const float2*)(bQ + kb + 2 * c);
#pragma unroll 4
        for (int sl = 0; sl < 24; ++sl) {
            float2 v = *(const float2*)(base + (size_t)sl * PSQ);
            s.x += v.x; s.y += v.y;
        }
        va[j] = s;
    }
    LOAD_B_NT(WK, DD)
    STORE_A()
    float* po = g_partP + (size_t)blockIdx.y * PS + blockIdx.x * 128;
    GEMM_COMPUTE_STORE(po, DD)
}

// ---- stage R (NT): A = sum(8 P-slots); B = Wr; out g_part slots 48..71
__global__ void __launch_bounds__(512, 1)
k_sgemmRf(const float* __restrict__ Wr) {
    __shared__ float As[32][98];
    __shared__ float Bs[32][132];
    const int tid = threadIdx.x;
    const int kb = blockIdx.y * 32;

    float2 va[3];
#pragma unroll
    for (int j = 0; j < 3; ++j) {
        int idx = tid + 512 * j; int m = idx >> 4, c = idx & 15;
        const float* base = g_partP + (size_t)m * DD + kb + 2 * c;
        float2 s = make_float2(0.f, 0.f);
#pragma unroll
        for (int sl = 0; sl < 8; ++sl) {
            float2 v = *(const float2*)(base + (size_t)sl * PS);
            s.x += v.x; s.y += v.y;
        }
        va[j] = s;
    }
    LOAD_B_NT(Wr, DD)
    STORE_A()
    float* po = g_part + (size_t)(48 + blockIdx.y) * PS + blockIdx.x * 128;
    GEMM_COMPUTE_STORE(po, DD)
}

// ---- stage Out (T, plain A = hbar): out slots 24..47 ----------------
__global__ void __launch_bounds__(512, 1)
k_sgemmOut(const float* __restrict__ Wr) {
    __shared__ float As[32][98];
    __shared__ float Bs[32][132];
    const int tid = threadIdx.x;
    const int kb = blockIdx.y * 32;

    float2 va[3];
#pragma unroll
    for (int j = 0; j < 3; ++j) {
        int idx = tid + 512 * j; int m = idx >> 4, c = idx & 15;
        va[j] = *(const float2*)(g_hbar + (size_t)m * DD + kb + 2 * c);
    }
    LOAD_B_T(Wr, DD)
    STORE_A()
    float* po = g_part + (size_t)(24 + blockIdx.y) * PS + blockIdx.x * 128;
    GEMM_COMPUTE_STORE(po, DD)
}

// ---------------- fused attention: R-reduce -> scores -> softmax -> hbar
__global__ void __launch_bounds__(256, 4)
k_attn(const float* __restrict__ hist) {
    __shared__ float Rs[DD];
    __shared__ float sc[104];
    __shared__ float red[2];
    const int b = blockIdx.x, tid = threadIdx.x;
    const int wid = tid >> 5, lane = tid & 31;
    const float* hb = hist + (size_t)b * LDH;

#pragma unroll
    for (int j = 0; j < 3; ++j) {
        int d = tid + 256 * j;
        const float* base = g_part + (size_t)48 * PS + (size_t)b * DD + d;
        float s = 0.f;
#pragma unroll 4
        for (int sl = 0; sl < 24; ++sl) s += base[(size_t)sl * PS];
        Rs[d] = s;
    }
    __syncthreads();

    for (int h = wid; h < HH; h += 8) {
        const float* row = hb + h * DD;
        float s = 0.f;
#pragma unroll 6
        for (int d = lane; d < DD; d += 32) s += row[d] * Rs[d];
#pragma unroll
        for (int o = 16; o; o >>= 1) s += __shfl_down_sync(0xffffffffu, s, o);
        if (lane == 0) sc[h] = s * (1.0f / 16.0f);
    }
    __syncthreads();

    if (wid == 0) {
        float v0 = sc[lane];
        float v1 = sc[lane + 32];
        float v2 = sc[lane + 64];
        float v3 = (lane + 96 < HH) ? sc[lane + 96] : -1e30f;
        float m = fmaxf(fmaxf(v0, v1), fmaxf(v2, v3));
#pragma unroll
        for (int o = 16; o; o >>= 1) m = fmaxf(m, __shfl_xor_sync(0xffffffffu, m, o));
        float e = __expf(v0 - m) + __expf(v1 - m) + __expf(v2 - m) +
                  ((lane + 96 < HH) ? __expf(v3 - m) : 0.f);
#pragma unroll
        for (int o = 16; o; o >>= 1) e += __shfl_xor_sync(0xffffffffu, e, o);
        if (lane == 0) { red[0] = m; red[1] = 1.0f / e; }
    }
    __syncthreads();
    if (tid < HH) sc[tid] = __expf(sc[tid] - red[0]) * red[1];
    __syncthreads();

    float s0 = 0.f, s1 = 0.f, s2 = 0.f;
    const float* p = hb + tid;
#pragma unroll 4
    for (int h = 0; h < HH; ++h) {
        float a = sc[h];
        s0 += a * p[h * DD];
        s1 += a * p[h * DD + 256];
        s2 += a * p[h * DD + 512];
    }
    g_hbar[b * DD + tid]       = s0;
    g_hbar[b * DD + tid + 256] = s1;
    g_hbar[b * DD + tid + 512] = s2;
}

// ---- final: out = sum(slots 0..47) + bl, broadcast over N -----------
__global__ void k_reduce_bcast(const float* __restrict__ bl, float* __restrict__ out) {
    int i = blockIdx.x * 256 + threadIdx.x;
    if (i >= BB * DD) return;
    float s = bl[i % DD];
#pragma unroll 4
    for (int ks = 0; ks < 48; ++ks) s += g_part[(size_t)ks * PS + i];
    int b = i / DD, d = i - b * DD;
    float* po = out + (size_t)b * NN * DD + d;
#pragma unroll 8
    for (int n = 0; n < NN; ++n) po[n * DD] = s;
}

// ---------------- launch ---------------------------------------------
extern "C" void kernel_launch(void* const* d_in, const int* in_sizes, int n_in,
                              void* d_out, int out_size) {
    (void)in_sizes; (void)n_in; (void)out_size;
    const float* hist = (const float*)d_in[0];
    const float* Wl = (const float*)d_in[2];
    const float* bl = (const float*)d_in[3];
    const float* Wr = (const float*)d_in[4];
    const float* WK = (const float*)d_in[5];
    const float* WQ = (const float*)d_in[6];
    const float* bQ = (const float*)d_in[7];

    void* p_neigh;
    cudaGetSymbolAddress(&p_neigh, g_neigh);

    k_neigh<<<BB, DD>>>(hist);
    // slots 0..23: neigh@Wl^T; slots 24..47: hist0@Wr^T
    k_sgemmA<<<dim3(6, 24, 2), 512>>>((const float*)p_neigh, Wl, hist, Wr);
    // Q partials: A = sum(48)+bl, B = WQ   (N=256, K=768)
    k_sgemmQf<<<dim3(2, 24), 512>>>(bl, WQ);
    // P partials: A = sum(24 Q)+bQ, B = WK (N=768, K=256)
    k_sgemmPf<<<dim3(6, 8), 512>>>(bQ, WK);
    // R partials: A = sum(8 P), B = Wr     (N=768, K=768) -> slots 48..71
    k_sgemmRf<<<dim3(6, 24), 512>>>(Wr);
    // R-reduce + scores + softmax + combine
    k_attn<<<BB, 256>>>(hist);
    // out partials: A = hbar, B = Wr -> slots 24..47
    k_sgemmOut<<<dim3(6, 24), 512>>>(Wr);
    // final: sum slots 0..47 + bl, broadcast
    k_reduce_bcast<<<(BB * DD + 255) / 256, 256>>>(bl, (float*)d_out);
}

// round 15
// speedup vs baseline: 1.4474x; 1.4474x over previous
#include <cuda_runtime.h>
#include <cstdint>

#define BB 96
#define HH 100
#define NN 128
#define DD 768
#define AA 256
#define LDH (HH * DD)      // hist batch stride
#define PS  (BB * DD)      // partial slot stride (N=768)

// ---------------- scratch ----------------
__device__ float g_neigh[BB * DD];
__device__ float g_bias [BB * DD];
__device__ float g_u    [BB * DD];
__device__ float g_Qv   [BB * AA];
__device__ float g_P    [BB * DD];
__device__ float g_R    [BB * DD];
__device__ float g_hbar [BB * DD];
__device__ float g_part [48 * PS];   // 2 jobs x 24 K-slots max

// ---------------- f32x2 helpers ----------------
typedef unsigned long long ull;
__device__ __forceinline__ ull pk2(float x) {
    ull r; asm("mov.b64 %0, {%1, %1};" : "=l"(r) : "f"(x)); return r;
}
__device__ __forceinline__ void ffma2(ull& d, ull a, ull b) {
    asm("fma.rn.f32x2 %0, %1, %2, %0;" : "+l"(d) : "l"(a), "l"(b));
}
__device__ __forceinline__ float2 up2(ull v) {
    float2 r; asm("mov.b64 {%0, %1}, %2;" : "=f"(r.x), "=f"(r.y) : "l"(v)); return r;
}

// ---------------- neigh = mean_{h<96} hist[b,h,:] ----------------
__global__ void k_neigh(const float* __restrict__ hist) {
    int b = blockIdx.x, d = threadIdx.x;           // 768 threads
    const float* p = hist + (size_t)b * LDH + d;
    float s = 0.f;
#pragma unroll 8
    for (int h = 0; h < BB; ++h) s += p[h * DD];
    g_neigh[b * DD + d] = s * (1.0f / BB);
}

// ======== shared GEMM body (f32x2): compute from As/Bs, store ========
// thread tile 6m x 4n; 16 x 32 thread grid.
#define GEMM_COMPUTE_STORE()                                                  \
    __syncthreads();                                                          \
    const int mI = tid >> 5, nI = tid & 31;                                   \
    ull acc[6][2];                                                            \
    _Pragma("unroll") for (int i = 0; i < 6; ++i)                             \
    { acc[i][0] = 0ULL; acc[i][1] = 0ULL; }                                   \
    _Pragma("unroll") for (int k = 0; k < 32; ++k) {                          \
        float2 a01 = *(const float2*)&As[k][6 * mI];                          \
        float2 a23 = *(const float2*)&As[k][6 * mI + 2];                      \
        float2 a45 = *(const float2*)&As[k][6 * mI + 4];                      \
        ulonglong2 bb = *(const ulonglong2*)&Bs[k][4 * nI];                   \
        ull ap0 = pk2(a01.x), ap1 = pk2(a01.y), ap2 = pk2(a23.x);             \
        ull ap3 = pk2(a23.y), ap4 = pk2(a45.x), ap5 = pk2(a45.y);             \
        ffma2(acc[0][0], ap0, bb.x); ffma2(acc[0][1], ap0, bb.y);             \
        ffma2(acc[1][0], ap1, bb.x); ffma2(acc[1][1], ap1, bb.y);             \
        ffma2(acc[2][0], ap2, bb.x); ffma2(acc[2][1], ap2, bb.y);             \
        ffma2(acc[3][0], ap3, bb.x); ffma2(acc[3][1], ap3, bb.y);             \
        ffma2(acc[4][0], ap4, bb.x); ffma2(acc[4][1], ap4, bb.y);             \
        ffma2(acc[5][0], ap5, bb.x); ffma2(acc[5][1], ap5, bb.y);             \
    }                                                                         \
    float* po = part + (size_t)slot * BB * N + blockIdx.x * 128;              \
    _Pragma("unroll") for (int i = 0; i < 6; ++i) {                           \
        int m = 6 * mI + i;                                                   \
        float2 lo = up2(acc[i][0]), hi = up2(acc[i][1]);                      \
        float4 v = make_float4(lo.x, lo.y, hi.x, hi.y);                       \
        *(float4*)&po[(size_t)m * N + 4 * nI] = v;                            \
    }

// ---- T layout: out[m,n] = sum_k A[m,k] * B[n,k] (B rows n, k-contig)
__global__ void __launch_bounds__(512, 2)
k_sgemmT(const float* __restrict__ A0, int lda0, const float* __restrict__ B0,
         const float* __restrict__ A1, int lda1, const float* __restrict__ B1,
         float* __restrict__ part, int N, int K) {
    __shared__ float As[32][98];
    __shared__ float Bs[32][132];
    const int tid = threadIdx.x;
    const int kb = blockIdx.y * 32;
    const int z = blockIdx.z;
    const int slot = z * 24 + blockIdx.y;
    const float* A = z ? A1 : A0;
    const float* B = z ? B1 : B0;
    const int lda = z ? lda1 : lda0;

    float2 va[3], vb[4];
#pragma unroll
    for (int j = 0; j < 3; ++j) {
        int idx = tid + 512 * j; int m = idx >> 4, c = idx & 15;
        va[j] = *(const float2*)(A + (size_t)m * lda + kb + 2 * c);
    }
#pragma unroll
    for (int j = 0; j < 4; ++j) {
        int idx = tid + 512 * j; int n = idx >> 4, c = idx & 15;
        vb[j] = *(const float2*)(B + (size_t)(blockIdx.x * 128 + n) * K + kb + 2 * c);
    }
#pragma unroll
    for (int j = 0; j < 3; ++j) {
        int idx = tid + 512 * j; int m = idx >> 4, c = idx & 15;
        As[2 * c][m] = va[j].x; As[2 * c + 1][m] = va[j].y;
    }
#pragma unroll
    for (int j = 0; j < 4; ++j) {
        int idx = tid + 512 * j; int n = idx >> 4, c = idx & 15;
        Bs[2 * c][n] = vb[j].x; Bs[2 * c + 1][n] = vb[j].y;
    }
    GEMM_COMPUTE_STORE()
}

// ---- NT layout: out[m,n] = sum_k A[m,k] * B[k,n] (B rows k, n-contig)
__global__ void __launch_bounds__(512, 2)
k_sgemmNT(const float* __restrict__ A, int lda, const float* __restrict__ B,
          int ldb, float* __restrict__ part, int N, int K) {
    __shared__ float As[32][98];
    __shared__ float Bs[32][132];
    const int tid = threadIdx.x;
    const int kb = blockIdx.y * 32;
    const int slot = blockIdx.y;

    float2 va[3];
    float4 wb[2];
#pragma unroll
    for (int j = 0; j < 3; ++j) {
        int idx = tid + 512 * j; int m = idx >> 4, c = idx & 15;
        va[j] = *(const float2*)(A + (size_t)m * lda + kb + 2 * c);
    }
#pragma unroll
    for (int j = 0; j < 2; ++j) {
        int vidx = tid + 512 * j; int k = vidx >> 5, nv = vidx & 31;
        wb[j] = *(const float4*)(B + (size_t)(kb + k) * ldb + blockIdx.x * 128 + 4 * nv);
    }
#pragma unroll
    for (int j = 0; j < 3; ++j) {
        int idx = tid + 512 * j; int m = idx >> 4, c = idx & 15;
        As[2 * c][m] = va[j].x; As[2 * c + 1][m] = va[j].y;
    }
#pragma unroll
    for (int j = 0; j < 2; ++j) {
        int vidx = tid + 512 * j; int k = vidx >> 5, nv = vidx & 31;
        *(float4*)&Bs[k][4 * nv] = wb[j];
    }
    GEMM_COMPUTE_STORE()
}

// ---------------- generic reduce: out = sum partials (+bias) ---------
// mode 0: +bias[n]; mode 2: none
__global__ void k_reduce(const float* __restrict__ bias, float* __restrict__ out,
                         int N, int KS, int mode) {
    int i = blockIdx.x * 256 + threadIdx.x;
    if (i >= BB * N) return;
    float s = 0.f;
    for (int ks = 0; ks < KS; ++ks) s += g_part[(size_t)ks * BB * N + i];
    if (mode == 0) s += bias[i % N];
    out[i] = s;
}

// ---- fused: bias = sum(0..23)+bl; u = sum(24..47)+bias --------------
__global__ void k_reduce2(const float* __restrict__ bl) {
    int i = blockIdx.x * 256 + threadIdx.x;
    if (i >= BB * DD) return;
    float sb = 0.f, su = 0.f;
#pragma unroll 4
    for (int ks = 0; ks < 24; ++ks) {
        sb += g_part[(size_t)ks * PS + i];
        su += g_part[(size_t)(24 + ks) * PS + i];
    }
    float bv = sb + bl[i % DD];
    g_bias[i] = bv;
    g_u[i] = su + bv;
}

// ---- final: out_flat = sum partials + bias, broadcast over N --------
__global__ void k_reduce_bcast(float* __restrict__ out) {
    int i = blockIdx.x * 256 + threadIdx.x;
    if (i >= BB * DD) return;
    float s = 0.f;
#pragma unroll 4
    for (int ks = 0; ks < 24; ++ks) s += g_part[(size_t)ks * PS + i];
    s += g_bias[i];
    int b = i / DD, d = i - b * DD;
    float* po = out + (size_t)b * NN * DD + d;
#pragma unroll 8
    for (int n = 0; n < NN; ++n) po[n * DD] = s;
}

// ---------------- fused attention: scores -> softmax -> hbar ---------
__global__ void __launch_bounds__(256, 4)
k_attn(const float* __restrict__ hist) {
    __shared__ float Rs[DD];
    __shared__ float sc[104];
    __shared__ float red[2];
    const int b = blockIdx.x, tid = threadIdx.x;
    const int wid = tid >> 5, lane = tid & 31;
    const float* hb = hist + (size_t)b * LDH;

#pragma unroll
    for (int j = 0; j < 3; ++j) Rs[tid + 256 * j] = g_R[b * DD + tid + 256 * j];
    __syncthreads();

    for (int h = wid; h < HH; h += 8) {
        const float* row = hb + h * DD;
        float s = 0.f;
#pragma unroll 6
        for (int d = lane; d < DD; d += 32) s += row[d] * Rs[d];
#pragma unroll
        for (int o = 16; o; o >>= 1) s += __shfl_down_sync(0xffffffffu, s, o);
        if (lane == 0) sc[h] = s * (1.0f / 16.0f);
    }
    __syncthreads();

    if (wid == 0) {
        float v0 = sc[lane];
        float v1 = sc[lane + 32];
        float v2 = sc[lane + 64];
        float v3 = (lane + 96 < HH) ? sc[lane + 96] : -1e30f;
        float m = fmaxf(fmaxf(v0, v1), fmaxf(v2, v3));
#pragma unroll
        for (int o = 16; o; o >>= 1) m = fmaxf(m, __shfl_xor_sync(0xffffffffu, m, o));
        float e = __expf(v0 - m) + __expf(v1 - m) + __expf(v2 - m) +
                  ((lane + 96 < HH) ? __expf(v3 - m) : 0.f);
#pragma unroll
        for (int o = 16; o; o >>= 1) e += __shfl_xor_sync(0xffffffffu, e, o);
        if (lane == 0) { red[0] = m; red[1] = 1.0f / e; }
    }
    __syncthreads();
    if (tid < HH) sc[tid] = __expf(sc[tid] - red[0]) * red[1];
    __syncthreads();

    float s0 = 0.f, s1 = 0.f, s2 = 0.f;
    const float* p = hb + tid;
#pragma unroll 4
    for (int h = 0; h < HH; ++h) {
        float a = sc[h];
        s0 += a * p[h * DD];
        s1 += a * p[h * DD + 256];
        s2 += a * p[h * DD + 512];
    }
    g_hbar[b * DD + tid]       = s0;
    g_hbar[b * DD + tid + 256] = s1;
    g_hbar[b * DD + tid + 512] = s2;
}

// ---------------- launch ---------------------------------------------
extern "C" void kernel_launch(void* const* d_in, const int* in_sizes, int n_in,
                              void* d_out, int out_size) {
    (void)in_sizes; (void)n_in; (void)out_size;
    const float* hist = (const float*)d_in[0];
    const float* Wl = (const float*)d_in[2];
    const float* bl = (const float*)d_in[3];
    const float* Wr = (const float*)d_in[4];
    const float* WK = (const float*)d_in[5];
    const float* WQ = (const float*)d_in[6];
    const float* bQ = (const float*)d_in[7];

    void *p_neigh, *p_u, *p_Q, *p_P, *p_R, *p_hbar, *p_part;
    cudaGetSymbolAddress(&p_neigh, g_neigh);
    cudaGetSymbolAddress(&p_u, g_u);
    cudaGetSymbolAddress(&p_Q, g_Qv);
    cudaGetSymbolAddress(&p_P, g_P);
    cudaGetSymbolAddress(&p_R, g_R);
    cudaGetSymbolAddress(&p_hbar, g_hbar);
    cudaGetSymbolAddress(&p_part, g_part);
    float* part = (float*)p_part;

    k_neigh<<<BB, DD>>>(hist);

    // z=0: bias_pre = neigh@Wl^T; z=1: u_pre = hist0@Wr^T
    k_sgemmT<<<dim3(6, 24, 2), 512>>>((const float*)p_neigh, DD, Wl,
                                      hist, LDH, Wr, part, DD, DD);
    k_reduce2<<<(BB * DD + 255) / 256, 256>>>(bl);

    // Q = u @ WQ^T + bQ   (N=256, K=768)
    k_sgemmT<<<dim3(2, 24, 1), 512>>>((const float*)p_u, DD, WQ,
                                      nullptr, 0, nullptr, part, AA, DD);
    k_reduce<<<(BB * AA + 255) / 256, 256>>>(bQ, (float*)p_Q, AA, 24, 0);

    // P = Q @ WK          (N=768, K=256; B rows k = WK rows)
    k_sgemmNT<<<dim3(6, 8, 1), 512>>>((const float*)p_Q, AA, WK, DD,
                                      part, DD, AA);
    k_reduce<<<(BB * DD + 255) / 256, 256>>>(nullptr, (float*)p_P, DD, 8, 2);

    // R = P @ Wr          (N=768, K=768; B rows k = Wr rows)
    k_sgemmNT<<<dim3(6, 24, 1), 512>>>((const float*)p_P, DD, Wr, DD,
                                       part, DD, DD);
    k_reduce<<<(BB * DD + 255) / 256, 256>>>(nullptr, (float*)p_R, DD, 24, 2);

    // scores -> softmax -> hbar
    k_attn<<<BB, 256>>>(hist);

    // out = hbar @ Wr^T + bias, broadcast over N
    k_sgemmT<<<dim3(6, 24, 1), 512>>>((const float*)p_hbar, DD, Wr,
                                      nullptr, 0, nullptr, part, DD, DD);
    k_reduce_bcast<<<(BB * DD + 255) / 256, 256>>>((float*)d_out);
}